// round 12
// baseline (speedup 1.0000x reference)
#include <cuda_runtime.h>

#define NN 15828
#define EE 253248
#define BB 64
#define HH 100
#define CAP 128                       // in-edge bucket capacity per node
#define KC 64                         // GEMM K-chunk (nodes per block)
#define NCH ((NN + KC - 1) / KC)      // 248 chunks

// ---------------- device scratch (zero-init at load; each call leaves the
// counters zeroed again so graph replays are deterministic) ----------------
__device__ int   g_cnt_out[NN];            // reset in k_prep
__device__ int   g_cnt_in[NN];             // reset in k_conv1 (after last read)
__device__ int   g_col[NN * CAP];          // in-edge source buckets
__device__ float g_doutr[NN];
__device__ float g_dinr[NN];
__device__ float g_x[NN * BB];             // feat * deg_out^-1/2
__device__ float g_y[NN * BB];             // conv0 out, pre-scaled by deg_out^-1/2
__device__ float g_h1[NN * BB];            // conv1 out (post leaky)
__device__ float g_part[NCH * BB * HH];    // GEMM split-K partials (6.35MB)
__device__ float g_A, g_B;                 // closed-form g(t) slopes
__device__ int   g_fastpath;               // 1 iff b0 == 0

// 1) One edge pass: bucket fill (by dst, storing src) + out-degree count.
__global__ void k_build(const int* __restrict__ ei) {
    int e = blockIdx.x * blockDim.x + threadIdx.x;
    if (e < EE) {
        int s = ei[e], d = ei[EE + e];
        atomicAdd(&g_cnt_out[s], 1);
        int pos = atomicAdd(&g_cnt_in[d], 1);
        if (pos < CAP) g_col[d * CAP + pos] = s;
    }
}

// 2) Norms + cnt_out reset + x pre-scale (warp per node) + g() slopes (block 0).
__global__ void k_prep(const float* __restrict__ feat,
                       const float* __restrict__ W0,
                       const float* __restrict__ b0,
                       const float* __restrict__ W1) {
    int t = threadIdx.x;
    if (blockIdx.x == 0) {
        __shared__ float sA[128], sB[128];
        int bad = 0;
        if (t < 128) {
            float a = 0.f, bb = 0.f;
            if (t < HH) {
                float w0 = W0[t], w1 = W1[t];
                float w = w0 * w1;
                a  = w * (w0 > 0.f ? 1.f : 0.01f);
                bb = w * (w0 > 0.f ? 0.01f : 1.f);
                if (b0[t] != 0.f) bad = 1;
            }
            sA[t] = a; sB[t] = bb;
        }
        int anybad = __syncthreads_or(bad);
        if (t == 0) {
            g_fastpath = anybad ? 0 : 1;
            float A = 0.f, B = 0.f;
#pragma unroll
            for (int i = 0; i < 128; i++) { A += sA[i]; B += sB[i]; }
            g_A = A; g_B = B;
        }
    }
    int warp = t >> 5, lane = t & 31;
    int node = blockIdx.x * 8 + warp;
    if (node >= NN) return;
    float dro;
    if (lane == 0) {
        int co = g_cnt_out[node];
        g_cnt_out[node] = 0;                          // clean for next call
        dro = rsqrtf((float)max(co, 1));
        g_doutr[node] = dro;
        g_dinr[node]  = rsqrtf((float)max(g_cnt_in[node], 1));
    }
    dro = __shfl_sync(0xffffffffu, dro, 0);
    const float2* f2 = reinterpret_cast<const float2*>(feat);
    float2* x2 = reinterpret_cast<float2*>(g_x);
    float2 v = f2[node * 32 + lane];
    x2[node * 32 + lane] = make_float2(v.x * dro, v.y * dro);
}

// 3) conv0: FOUR nodes per warp with interleaved gather chains (4x MLP).
//    gather x over in-bucket, deg_in norm, closed-form g(), deg_out pre-scale.
__global__ void k_conv0(const float* __restrict__ W0,
                        const float* __restrict__ b0,
                        const float* __restrict__ W1) {
    __shared__ float sW0[HH], sb0[HH], sW1[HH];
    int t = threadIdx.x;
    int fast = g_fastpath;
    if (!fast && t < HH) { sW0[t] = W0[t]; sb0[t] = b0[t]; sW1[t] = W1[t]; }
    __syncthreads();

    int warp = t >> 5, lane = t & 31;
    int base = blockIdx.x * 32 + warp;          // 8 warps x 4 nodes, stride 8
    if (base >= NN) return;

    int   n[4];
    int   cnt[4], k4[4];
    const int4* cp[4];
    float aX[4], aY[4], bX[4], bY[4];
#pragma unroll
    for (int i = 0; i < 4; i++) {
        n[i] = base + 8 * i;
        bool has = (n[i] < NN);
        cnt[i] = has ? min(g_cnt_in[n[i]], CAP) : 0;
        k4[i] = cnt[i] >> 2;
        cp[i] = reinterpret_cast<const int4*>(g_col + n[i] * CAP);
        aX[i] = 0.f; aY[i] = 0.f; bX[i] = 0.f; bY[i] = 0.f;
    }
    const float2* x2 = reinterpret_cast<const float2*>(g_x);

    int kmax = max(max(k4[0], k4[1]), max(k4[2], k4[3]));
    for (int k = 0; k < kmax; k++) {
#pragma unroll
        for (int i = 0; i < 4; i++) {
            if (k < k4[i]) {
                int4 c = cp[i][k];
                float2 v0 = x2[c.x * 32 + lane];
                float2 v1 = x2[c.y * 32 + lane];
                float2 v2 = x2[c.z * 32 + lane];
                float2 v3 = x2[c.w * 32 + lane];
                aX[i] += v0.x; aY[i] += v0.y;
                bX[i] += v1.x; bY[i] += v1.y;
                aX[i] += v2.x; aY[i] += v2.y;
                bX[i] += v3.x; bY[i] += v3.y;
            }
        }
    }
#pragma unroll
    for (int i = 0; i < 4; i++)
        for (int e = k4[i] << 2; e < cnt[i]; e++) {
            float2 v = x2[g_col[n[i] * CAP + e] * 32 + lane];
            aX[i] += v.x; aY[i] += v.y;
        }

    float2* y2 = reinterpret_cast<float2*>(g_y);
    float A = g_A, Bs = g_B;
#pragma unroll
    for (int i = 0; i < 4; i++) {
        if (n[i] >= NN) break;
        float dr = g_dinr[n[i]];
        float tx = (aX[i] + bX[i]) * dr, ty = (aY[i] + bY[i]) * dr;
        float yx, yy;
        if (fast) {
            yx = (tx > 0.f ? A : Bs) * tx;
            yy = (ty > 0.f ? A : Bs) * ty;
        } else {
            yx = 0.f; yy = 0.f;
#pragma unroll 4
            for (int f = 0; f < HH; f++) {
                float vx = fmaf(tx, sW0[f], sb0[f]);
                float vy = fmaf(ty, sW0[f], sb0[f]);
                vx = fmaxf(vx, 0.01f * vx);
                vy = fmaxf(vy, 0.01f * vy);
                yx = fmaf(vx, sW1[f], yx);
                yy = fmaf(vy, sW1[f], yy);
            }
        }
        float dro = g_doutr[n[i]];
        y2[n[i] * 32 + lane] = make_float2(yx * dro, yy * dro);
    }
}

// 4) conv1: FOUR nodes per warp, interleaved chains. gather y, deg_in norm,
//    bias, leaky -> h1. Resets cnt_in.
__global__ void k_conv1(const float* __restrict__ b1) {
    int t = threadIdx.x;
    int warp = t >> 5, lane = t & 31;
    int base = blockIdx.x * 32 + warp;
    if (base >= NN) return;

    int   n[4];
    int   cnt[4], k4[4];
    const int4* cp[4];
    float aX[4], aY[4], bX[4], bY[4];
#pragma unroll
    for (int i = 0; i < 4; i++) {
        n[i] = base + 8 * i;
        bool has = (n[i] < NN);
        cnt[i] = has ? min(g_cnt_in[n[i]], CAP) : 0;
        k4[i] = cnt[i] >> 2;
        cp[i] = reinterpret_cast<const int4*>(g_col + n[i] * CAP);
        aX[i] = 0.f; aY[i] = 0.f; bX[i] = 0.f; bY[i] = 0.f;
        if (has && lane == 0) g_cnt_in[n[i]] = 0;   // clean for next call
    }
    const float2* y2 = reinterpret_cast<const float2*>(g_y);

    int kmax = max(max(k4[0], k4[1]), max(k4[2], k4[3]));
    for (int k = 0; k < kmax; k++) {
#pragma unroll
        for (int i = 0; i < 4; i++) {
            if (k < k4[i]) {
                int4 c = cp[i][k];
                float2 v0 = y2[c.x * 32 + lane];
                float2 v1 = y2[c.y * 32 + lane];
                float2 v2 = y2[c.z * 32 + lane];
                float2 v3 = y2[c.w * 32 + lane];
                aX[i] += v0.x; aY[i] += v0.y;
                bX[i] += v1.x; bY[i] += v1.y;
                aX[i] += v2.x; aY[i] += v2.y;
                bX[i] += v3.x; bY[i] += v3.y;
            }
        }
    }
#pragma unroll
    for (int i = 0; i < 4; i++)
        for (int e = k4[i] << 2; e < cnt[i]; e++) {
            float2 v = y2[g_col[n[i] * CAP + e] * 32 + lane];
            aX[i] += v.x; aY[i] += v.y;
        }

    float bias = b1[0];
    float2* h2 = reinterpret_cast<float2*>(g_h1);
#pragma unroll
    for (int i = 0; i < 4; i++) {
        if (n[i] >= NN) break;
        float dr = g_dinr[n[i]];
        float vx = fmaf(aX[i] + bX[i], dr, bias);
        float vy = fmaf(aY[i] + bY[i], dr, bias);
        h2[n[i] * 32 + lane] =
            make_float2(fmaxf(vx, 0.01f * vx), fmaxf(vy, 0.01f * vy));
    }
}

// 5) Pure split-K GEMM: part[ch][b,j] = sum_{n in chunk} h1[n,b]*lw0[j,n].
//    512 threads; 400 compute threads with 4j x 4b register tiles.
__global__ void __launch_bounds__(512) k_gemm(const float* __restrict__ lw0) {
    __shared__ float slw[KC * 104];    // [nn][j], stride 104 (16B-aligned rows)
    __shared__ float sh1[KC][BB];      // [nn][b] 16KB
    int t = threadIdx.x;
    int n0 = blockIdx.x * KC;

    for (int idx = t; idx < HH * KC; idx += 512) {
        int j = idx >> 6, nn = idx & 63;
        int n = n0 + nn;
        slw[nn * 104 + j] = (n < NN) ? lw0[j * NN + n] : 0.f;
    }
    const float4* h4 = reinterpret_cast<const float4*>(g_h1);
    for (int idx = t; idx < KC * 16; idx += 512) {
        int nn = idx >> 4, q = idx & 15;
        int n = n0 + nn;
        reinterpret_cast<float4*>(&sh1[nn][0])[q] =
            (n < NN) ? h4[n * 16 + q] : make_float4(0.f, 0.f, 0.f, 0.f);
    }
    __syncthreads();

    if (t >= 400) return;
    int jtile = t >> 4;    // 25 tiles of 4 j
    int btile = t & 15;    // 16 tiles of 4 b
    float acc[4][4];
#pragma unroll
    for (int a = 0; a < 4; a++)
#pragma unroll
        for (int b = 0; b < 4; b++) acc[a][b] = 0.f;

#pragma unroll 8
    for (int nn = 0; nn < KC; nn++) {
        float4 w = *reinterpret_cast<const float4*>(&slw[nn * 104 + jtile * 4]);
        float4 h = *reinterpret_cast<const float4*>(&sh1[nn][btile * 4]);
        acc[0][0] = fmaf(w.x, h.x, acc[0][0]);
        acc[0][1] = fmaf(w.x, h.y, acc[0][1]);
        acc[0][2] = fmaf(w.x, h.z, acc[0][2]);
        acc[0][3] = fmaf(w.x, h.w, acc[0][3]);
        acc[1][0] = fmaf(w.y, h.x, acc[1][0]);
        acc[1][1] = fmaf(w.y, h.y, acc[1][1]);
        acc[1][2] = fmaf(w.y, h.z, acc[1][2]);
        acc[1][3] = fmaf(w.y, h.w, acc[1][3]);
        acc[2][0] = fmaf(w.z, h.x, acc[2][0]);
        acc[2][1] = fmaf(w.z, h.y, acc[2][1]);
        acc[2][2] = fmaf(w.z, h.z, acc[2][2]);
        acc[2][3] = fmaf(w.z, h.w, acc[2][3]);
        acc[3][0] = fmaf(w.w, h.x, acc[3][0]);
        acc[3][1] = fmaf(w.w, h.y, acc[3][1]);
        acc[3][2] = fmaf(w.w, h.z, acc[3][2]);
        acc[3][3] = fmaf(w.w, h.w, acc[3][3]);
    }
    float* dst = g_part + blockIdx.x * (BB * HH);
#pragma unroll
    for (int b4 = 0; b4 < 4; b4++) {
        int b = btile * 4 + b4;
        float4 v = make_float4(acc[0][b4], acc[1][b4], acc[2][b4], acc[3][b4]);
        *reinterpret_cast<float4*>(&dst[b * HH + jtile * 4]) = v;
    }
}

// 6) Head: reduce 248 partials (4 slices of 62), then the 3-layer leaky MLP.
__global__ void k_head(const float* __restrict__ lb0,
                       const float* __restrict__ lw2,
                       const float* __restrict__ lb2,
                       const float* __restrict__ lw3,
                       const float* __restrict__ lb3,
                       float* __restrict__ out) {
    __shared__ float part[4][HH];
    __shared__ float s0[HH], s1[HH];
    int b = blockIdx.x, t = threadIdx.x;   // 512 threads
    int s = t >> 7, jj = t & 127;
    const int SL = (NCH + 3) / 4;          // 62
    if (jj < HH) {
        float a = 0.f;
        int c0 = s * SL, c1 = min(c0 + SL, NCH);
#pragma unroll 4
        for (int c = c0; c < c1; c++) a += g_part[c * (BB * HH) + b * HH + jj];
        part[s][jj] = a;
    }
    __syncthreads();
    if (t < HH) {
        float v = part[0][t] + part[1][t] + part[2][t] + part[3][t] + lb0[t];
        s0[t] = fmaxf(v, 0.01f * v);
    }
    __syncthreads();
    if (t < HH) {
        float a = lb2[t];
#pragma unroll 4
        for (int k = 0; k < HH; k++) a = fmaf(s0[k], lw2[t * HH + k], a);
        s1[t] = fmaxf(a, 0.01f * a);
    }
    __syncthreads();
    if (t < 10) {
        float a = lb3[t];
#pragma unroll 4
        for (int k = 0; k < HH; k++) a = fmaf(s1[k], lw3[t * HH + k], a);
        out[b * 10 + t] = fmaxf(a, 0.01f * a);
    }
}

// ---------------- launch ----------------
extern "C" void kernel_launch(void* const* d_in, const int* in_sizes, int n_in,
                              void* d_out, int out_size) {
    const float* in_feat = (const float*)d_in[0];
    const int*   ei      = (const int*)d_in[1];
    const float* W0      = (const float*)d_in[2];
    const float* b0      = (const float*)d_in[3];
    const float* W1      = (const float*)d_in[4];
    const float* b1      = (const float*)d_in[5];
    const float* lw0     = (const float*)d_in[6];
    const float* lb0     = (const float*)d_in[7];
    const float* lw2     = (const float*)d_in[8];
    const float* lb2     = (const float*)d_in[9];
    const float* lw3     = (const float*)d_in[10];
    const float* lb3     = (const float*)d_in[11];
    float* out = (float*)d_out;

    k_build<<<(EE + 255) / 256, 256>>>(ei);
    k_prep<<<(NN + 7) / 8, 256>>>(in_feat, W0, b0, W1);
    k_conv0<<<(NN + 31) / 32, 256>>>(W0, b0, W1);
    k_conv1<<<(NN + 31) / 32, 256>>>(b1);
    k_gemm<<<NCH, 512>>>(lw0);
    k_head<<<BB, 512>>>(lb0, lw2, lb2, lw3, lb3, out);
}

// round 13
// speedup vs baseline: 1.1555x; 1.1555x over previous
#include <cuda_runtime.h>

#define NN 15828
#define EE 253248
#define BB 64
#define HH 100
#define CAP 128                       // in-edge bucket capacity per node
#define KC 64                         // GEMM K-chunk (nodes per block)
#define NCH ((NN + KC - 1) / KC)      // 248 chunks

// ---------------- device scratch (zero-init at load; each call leaves the
// counters zeroed again so graph replays are deterministic) ----------------
__device__ int   g_cnt_out[NN];            // reset in k_prep
__device__ int   g_cnt_in[NN];             // reset in k_conv1 (after last read)
__device__ int   g_col[NN * CAP];          // in-edge source buckets
__device__ float g_doutr[NN];
__device__ float g_dinr[NN];
__device__ float g_x[NN * BB];             // feat * deg_out^-1/2
__device__ float g_y[NN * BB];             // conv0 out, pre-scaled by deg_out^-1/2
__device__ float g_h1[NN * BB];            // conv1 out (post leaky)
__device__ float g_part[NCH * BB * HH];    // GEMM split-K partials (6.35MB)
__device__ float g_A, g_B;                 // closed-form g(t) slopes
__device__ int   g_fastpath;               // 1 iff b0 == 0

// 1) One edge pass: bucket fill (by dst, storing src) + out-degree count.
__global__ void k_build(const int* __restrict__ ei) {
    int e = blockIdx.x * blockDim.x + threadIdx.x;
    if (e < EE) {
        int s = ei[e], d = ei[EE + e];
        atomicAdd(&g_cnt_out[s], 1);
        int pos = atomicAdd(&g_cnt_in[d], 1);
        if (pos < CAP) g_col[d * CAP + pos] = s;
    }
}

// 2) Norms + cnt_out reset + x pre-scale (warp per node) + g() slopes (block 0).
__global__ void k_prep(const float* __restrict__ feat,
                       const float* __restrict__ W0,
                       const float* __restrict__ b0,
                       const float* __restrict__ W1) {
    int t = threadIdx.x;
    if (blockIdx.x == 0) {
        __shared__ float sA[128], sB[128];
        int bad = 0;
        if (t < 128) {
            float a = 0.f, bb = 0.f;
            if (t < HH) {
                float w0 = W0[t], w1 = W1[t];
                float w = w0 * w1;
                a  = w * (w0 > 0.f ? 1.f : 0.01f);
                bb = w * (w0 > 0.f ? 0.01f : 1.f);
                if (b0[t] != 0.f) bad = 1;
            }
            sA[t] = a; sB[t] = bb;
        }
        int anybad = __syncthreads_or(bad);
        if (t == 0) {
            g_fastpath = anybad ? 0 : 1;
            float A = 0.f, B = 0.f;
#pragma unroll
            for (int i = 0; i < 128; i++) { A += sA[i]; B += sB[i]; }
            g_A = A; g_B = B;
        }
    }
    int warp = t >> 5, lane = t & 31;
    int node = blockIdx.x * 8 + warp;
    if (node >= NN) return;
    float dro;
    if (lane == 0) {
        int co = g_cnt_out[node];
        g_cnt_out[node] = 0;                          // clean for next call
        dro = rsqrtf((float)max(co, 1));
        g_doutr[node] = dro;
        g_dinr[node]  = rsqrtf((float)max(g_cnt_in[node], 1));
    }
    dro = __shfl_sync(0xffffffffu, dro, 0);
    const float2* f2 = reinterpret_cast<const float2*>(feat);
    float2* x2 = reinterpret_cast<float2*>(g_x);
    float2 v = f2[node * 32 + lane];
    x2[node * 32 + lane] = make_float2(v.x * dro, v.y * dro);
}

// 3) conv0: THREE nodes per warp, fully scalar interleaved gather chains.
//    gather x over in-bucket, deg_in norm, closed-form g(), deg_out pre-scale.
__global__ void k_conv0(const float* __restrict__ W0,
                        const float* __restrict__ b0,
                        const float* __restrict__ W1) {
    __shared__ float sW0[HH], sb0[HH], sW1[HH];
    int t = threadIdx.x;
    int fast = g_fastpath;
    if (!fast && t < HH) { sW0[t] = W0[t]; sb0[t] = b0[t]; sW1[t] = W1[t]; }
    __syncthreads();

    int warp = t >> 5, lane = t & 31;
    int nA = blockIdx.x * 24 + warp;        // 8 warps x 3 nodes, stride 8
    int nB = nA + 8;
    int nC = nA + 16;
    if (nA >= NN) return;
    bool hasB = (nB < NN), hasC = (nC < NN);

    int cntA = min(g_cnt_in[nA], CAP);
    int cntB = hasB ? min(g_cnt_in[nB], CAP) : 0;
    int cntC = hasC ? min(g_cnt_in[nC], CAP) : 0;
    const int4* cA = reinterpret_cast<const int4*>(g_col + nA * CAP);
    const int4* cB = reinterpret_cast<const int4*>(g_col + nB * CAP);
    const int4* cC = reinterpret_cast<const int4*>(g_col + nC * CAP);
    const float2* x2 = reinterpret_cast<const float2*>(g_x);

    float aX0 = 0.f, aY0 = 0.f, aX1 = 0.f, aY1 = 0.f;
    float bX0 = 0.f, bY0 = 0.f, bX1 = 0.f, bY1 = 0.f;
    float cX0 = 0.f, cY0 = 0.f, cX1 = 0.f, cY1 = 0.f;
    int k4A = cntA >> 2, k4B = cntB >> 2, k4C = cntC >> 2;
    int kmax = max(k4A, max(k4B, k4C));
    for (int k = 0; k < kmax; k++) {
        if (k < k4A) {
            int4 c = cA[k];
            float2 v0 = x2[c.x * 32 + lane];
            float2 v1 = x2[c.y * 32 + lane];
            float2 v2 = x2[c.z * 32 + lane];
            float2 v3 = x2[c.w * 32 + lane];
            aX0 += v0.x; aY0 += v0.y;
            aX1 += v1.x; aY1 += v1.y;
            aX0 += v2.x; aY0 += v2.y;
            aX1 += v3.x; aY1 += v3.y;
        }
        if (k < k4B) {
            int4 c = cB[k];
            float2 v0 = x2[c.x * 32 + lane];
            float2 v1 = x2[c.y * 32 + lane];
            float2 v2 = x2[c.z * 32 + lane];
            float2 v3 = x2[c.w * 32 + lane];
            bX0 += v0.x; bY0 += v0.y;
            bX1 += v1.x; bY1 += v1.y;
            bX0 += v2.x; bY0 += v2.y;
            bX1 += v3.x; bY1 += v3.y;
        }
        if (k < k4C) {
            int4 c = cC[k];
            float2 v0 = x2[c.x * 32 + lane];
            float2 v1 = x2[c.y * 32 + lane];
            float2 v2 = x2[c.z * 32 + lane];
            float2 v3 = x2[c.w * 32 + lane];
            cX0 += v0.x; cY0 += v0.y;
            cX1 += v1.x; cY1 += v1.y;
            cX0 += v2.x; cY0 += v2.y;
            cX1 += v3.x; cY1 += v3.y;
        }
    }
    for (int e = k4A << 2; e < cntA; e++) {
        float2 v = x2[g_col[nA * CAP + e] * 32 + lane];
        aX0 += v.x; aY0 += v.y;
    }
    for (int e = k4B << 2; e < cntB; e++) {
        float2 v = x2[g_col[nB * CAP + e] * 32 + lane];
        bX0 += v.x; bY0 += v.y;
    }
    for (int e = k4C << 2; e < cntC; e++) {
        float2 v = x2[g_col[nC * CAP + e] * 32 + lane];
        cX0 += v.x; cY0 += v.y;
    }

    float2* y2 = reinterpret_cast<float2*>(g_y);
    float A = g_A, Bs = g_B;
    {   // node A
        float dr = g_dinr[nA];
        float tx = (aX0 + aX1) * dr, ty = (aY0 + aY1) * dr;
        float yx, yy;
        if (fast) {
            yx = (tx > 0.f ? A : Bs) * tx;
            yy = (ty > 0.f ? A : Bs) * ty;
        } else {
            yx = 0.f; yy = 0.f;
#pragma unroll 4
            for (int f = 0; f < HH; f++) {
                float vx = fmaf(tx, sW0[f], sb0[f]);
                float vy = fmaf(ty, sW0[f], sb0[f]);
                vx = fmaxf(vx, 0.01f * vx);
                vy = fmaxf(vy, 0.01f * vy);
                yx = fmaf(vx, sW1[f], yx);
                yy = fmaf(vy, sW1[f], yy);
            }
        }
        float dro = g_doutr[nA];
        y2[nA * 32 + lane] = make_float2(yx * dro, yy * dro);
    }
    if (hasB) {
        float dr = g_dinr[nB];
        float tx = (bX0 + bX1) * dr, ty = (bY0 + bY1) * dr;
        float yx, yy;
        if (fast) {
            yx = (tx > 0.f ? A : Bs) * tx;
            yy = (ty > 0.f ? A : Bs) * ty;
        } else {
            yx = 0.f; yy = 0.f;
#pragma unroll 4
            for (int f = 0; f < HH; f++) {
                float vx = fmaf(tx, sW0[f], sb0[f]);
                float vy = fmaf(ty, sW0[f], sb0[f]);
                vx = fmaxf(vx, 0.01f * vx);
                vy = fmaxf(vy, 0.01f * vy);
                yx = fmaf(vx, sW1[f], yx);
                yy = fmaf(vy, sW1[f], yy);
            }
        }
        float dro = g_doutr[nB];
        y2[nB * 32 + lane] = make_float2(yx * dro, yy * dro);
    }
    if (hasC) {
        float dr = g_dinr[nC];
        float tx = (cX0 + cX1) * dr, ty = (cY0 + cY1) * dr;
        float yx, yy;
        if (fast) {
            yx = (tx > 0.f ? A : Bs) * tx;
            yy = (ty > 0.f ? A : Bs) * ty;
        } else {
            yx = 0.f; yy = 0.f;
#pragma unroll 4
            for (int f = 0; f < HH; f++) {
                float vx = fmaf(tx, sW0[f], sb0[f]);
                float vy = fmaf(ty, sW0[f], sb0[f]);
                vx = fmaxf(vx, 0.01f * vx);
                vy = fmaxf(vy, 0.01f * vy);
                yx = fmaf(vx, sW1[f], yx);
                yy = fmaf(vy, sW1[f], yy);
            }
        }
        float dro = g_doutr[nC];
        y2[nC * 32 + lane] = make_float2(yx * dro, yy * dro);
    }
}

// 4) conv1: THREE nodes per warp, fully scalar interleaved chains.
//    gather y, deg_in norm, bias, leaky -> h1. Resets cnt_in.
__global__ void k_conv1(const float* __restrict__ b1) {
    int t = threadIdx.x;
    int warp = t >> 5, lane = t & 31;
    int nA = blockIdx.x * 24 + warp;
    int nB = nA + 8;
    int nC = nA + 16;
    if (nA >= NN) return;
    bool hasB = (nB < NN), hasC = (nC < NN);

    int cntA = min(g_cnt_in[nA], CAP);
    int cntB = hasB ? min(g_cnt_in[nB], CAP) : 0;
    int cntC = hasC ? min(g_cnt_in[nC], CAP) : 0;
    if (lane == 0) {
        g_cnt_in[nA] = 0;                      // clean for next call
        if (hasB) g_cnt_in[nB] = 0;
        if (hasC) g_cnt_in[nC] = 0;
    }
    const int4* cA = reinterpret_cast<const int4*>(g_col + nA * CAP);
    const int4* cB = reinterpret_cast<const int4*>(g_col + nB * CAP);
    const int4* cC = reinterpret_cast<const int4*>(g_col + nC * CAP);
    const float2* y2 = reinterpret_cast<const float2*>(g_y);

    float aX0 = 0.f, aY0 = 0.f, aX1 = 0.f, aY1 = 0.f;
    float bX0 = 0.f, bY0 = 0.f, bX1 = 0.f, bY1 = 0.f;
    float cX0 = 0.f, cY0 = 0.f, cX1 = 0.f, cY1 = 0.f;
    int k4A = cntA >> 2, k4B = cntB >> 2, k4C = cntC >> 2;
    int kmax = max(k4A, max(k4B, k4C));
    for (int k = 0; k < kmax; k++) {
        if (k < k4A) {
            int4 c = cA[k];
            float2 v0 = y2[c.x * 32 + lane];
            float2 v1 = y2[c.y * 32 + lane];
            float2 v2 = y2[c.z * 32 + lane];
            float2 v3 = y2[c.w * 32 + lane];
            aX0 += v0.x; aY0 += v0.y;
            aX1 += v1.x; aY1 += v1.y;
            aX0 += v2.x; aY0 += v2.y;
            aX1 += v3.x; aY1 += v3.y;
        }
        if (k < k4B) {
            int4 c = cB[k];
            float2 v0 = y2[c.x * 32 + lane];
            float2 v1 = y2[c.y * 32 + lane];
            float2 v2 = y2[c.z * 32 + lane];
            float2 v3 = y2[c.w * 32 + lane];
            bX0 += v0.x; bY0 += v0.y;
            bX1 += v1.x; bY1 += v1.y;
            bX0 += v2.x; bY0 += v2.y;
            bX1 += v3.x; bY1 += v3.y;
        }
        if (k < k4C) {
            int4 c = cC[k];
            float2 v0 = y2[c.x * 32 + lane];
            float2 v1 = y2[c.y * 32 + lane];
            float2 v2 = y2[c.z * 32 + lane];
            float2 v3 = y2[c.w * 32 + lane];
            cX0 += v0.x; cY0 += v0.y;
            cX1 += v1.x; cY1 += v1.y;
            cX0 += v2.x; cY0 += v2.y;
            cX1 += v3.x; cY1 += v3.y;
        }
    }
    for (int e = k4A << 2; e < cntA; e++) {
        float2 v = y2[g_col[nA * CAP + e] * 32 + lane];
        aX0 += v.x; aY0 += v.y;
    }
    for (int e = k4B << 2; e < cntB; e++) {
        float2 v = y2[g_col[nB * CAP + e] * 32 + lane];
        bX0 += v.x; bY0 += v.y;
    }
    for (int e = k4C << 2; e < cntC; e++) {
        float2 v = y2[g_col[nC * CAP + e] * 32 + lane];
        cX0 += v.x; cY0 += v.y;
    }

    float bias = b1[0];
    float2* h2 = reinterpret_cast<float2*>(g_h1);
    {
        float dr = g_dinr[nA];
        float vx = fmaf(aX0 + aX1, dr, bias);
        float vy = fmaf(aY0 + aY1, dr, bias);
        h2[nA * 32 + lane] = make_float2(fmaxf(vx, 0.01f * vx), fmaxf(vy, 0.01f * vy));
    }
    if (hasB) {
        float dr = g_dinr[nB];
        float vx = fmaf(bX0 + bX1, dr, bias);
        float vy = fmaf(bY0 + bY1, dr, bias);
        h2[nB * 32 + lane] = make_float2(fmaxf(vx, 0.01f * vx), fmaxf(vy, 0.01f * vy));
    }
    if (hasC) {
        float dr = g_dinr[nC];
        float vx = fmaf(cX0 + cX1, dr, bias);
        float vy = fmaf(cY0 + cY1, dr, bias);
        h2[nC * 32 + lane] = make_float2(fmaxf(vx, 0.01f * vx), fmaxf(vy, 0.01f * vy));
    }
}

// 5) Pure split-K GEMM: part[ch][b,j] = sum_{n in chunk} h1[n,b]*lw0[j,n].
//    512 threads; 400 compute threads with 4j x 4b register tiles.
__global__ void __launch_bounds__(512) k_gemm(const float* __restrict__ lw0) {
    __shared__ float slw[KC * 104];    // [nn][j], stride 104 (16B-aligned rows)
    __shared__ float sh1[KC][BB];      // [nn][b] 16KB
    int t = threadIdx.x;
    int n0 = blockIdx.x * KC;

    for (int idx = t; idx < HH * KC; idx += 512) {
        int j = idx >> 6, nn = idx & 63;
        int n = n0 + nn;
        slw[nn * 104 + j] = (n < NN) ? lw0[j * NN + n] : 0.f;
    }
    const float4* h4 = reinterpret_cast<const float4*>(g_h1);
    for (int idx = t; idx < KC * 16; idx += 512) {
        int nn = idx >> 4, q = idx & 15;
        int n = n0 + nn;
        reinterpret_cast<float4*>(&sh1[nn][0])[q] =
            (n < NN) ? h4[n * 16 + q] : make_float4(0.f, 0.f, 0.f, 0.f);
    }
    __syncthreads();

    if (t >= 400) return;
    int jtile = t >> 4;    // 25 tiles of 4 j
    int btile = t & 15;    // 16 tiles of 4 b
    float acc[4][4];
#pragma unroll
    for (int a = 0; a < 4; a++)
#pragma unroll
        for (int b = 0; b < 4; b++) acc[a][b] = 0.f;

#pragma unroll 8
    for (int nn = 0; nn < KC; nn++) {
        float4 w = *reinterpret_cast<const float4*>(&slw[nn * 104 + jtile * 4]);
        float4 h = *reinterpret_cast<const float4*>(&sh1[nn][btile * 4]);
        acc[0][0] = fmaf(w.x, h.x, acc[0][0]);
        acc[0][1] = fmaf(w.x, h.y, acc[0][1]);
        acc[0][2] = fmaf(w.x, h.z, acc[0][2]);
        acc[0][3] = fmaf(w.x, h.w, acc[0][3]);
        acc[1][0] = fmaf(w.y, h.x, acc[1][0]);
        acc[1][1] = fmaf(w.y, h.y, acc[1][1]);
        acc[1][2] = fmaf(w.y, h.z, acc[1][2]);
        acc[1][3] = fmaf(w.y, h.w, acc[1][3]);
        acc[2][0] = fmaf(w.z, h.x, acc[2][0]);
        acc[2][1] = fmaf(w.z, h.y, acc[2][1]);
        acc[2][2] = fmaf(w.z, h.z, acc[2][2]);
        acc[2][3] = fmaf(w.z, h.w, acc[2][3]);
        acc[3][0] = fmaf(w.w, h.x, acc[3][0]);
        acc[3][1] = fmaf(w.w, h.y, acc[3][1]);
        acc[3][2] = fmaf(w.w, h.z, acc[3][2]);
        acc[3][3] = fmaf(w.w, h.w, acc[3][3]);
    }
    float* dst = g_part + blockIdx.x * (BB * HH);
#pragma unroll
    for (int b4 = 0; b4 < 4; b4++) {
        int b = btile * 4 + b4;
        float4 v = make_float4(acc[0][b4], acc[1][b4], acc[2][b4], acc[3][b4]);
        *reinterpret_cast<float4*>(&dst[b * HH + jtile * 4]) = v;
    }
}

// 6) Head: reduce 248 partials (4 slices of 62), then the 3-layer leaky MLP.
__global__ void k_head(const float* __restrict__ lb0,
                       const float* __restrict__ lw2,
                       const float* __restrict__ lb2,
                       const float* __restrict__ lw3,
                       const float* __restrict__ lb3,
                       float* __restrict__ out) {
    __shared__ float part[4][HH];
    __shared__ float s0[HH], s1[HH];
    int b = blockIdx.x, t = threadIdx.x;   // 512 threads
    int s = t >> 7, jj = t & 127;
    const int SL = (NCH + 3) / 4;          // 62
    if (jj < HH) {
        float a = 0.f;
        int c0 = s * SL, c1 = min(c0 + SL, NCH);
#pragma unroll 4
        for (int c = c0; c < c1; c++) a += g_part[c * (BB * HH) + b * HH + jj];
        part[s][jj] = a;
    }
    __syncthreads();
    if (t < HH) {
        float v = part[0][t] + part[1][t] + part[2][t] + part[3][t] + lb0[t];
        s0[t] = fmaxf(v, 0.01f * v);
    }
    __syncthreads();
    if (t < HH) {
        float a = lb2[t];
#pragma unroll 4
        for (int k = 0; k < HH; k++) a = fmaf(s0[k], lw2[t * HH + k], a);
        s1[t] = fmaxf(a, 0.01f * a);
    }
    __syncthreads();
    if (t < 10) {
        float a = lb3[t];
#pragma unroll 4
        for (int k = 0; k < HH; k++) a = fmaf(s1[k], lw3[t * HH + k], a);
        out[b * 10 + t] = fmaxf(a, 0.01f * a);
    }
}

// ---------------- launch ----------------
extern "C" void kernel_launch(void* const* d_in, const int* in_sizes, int n_in,
                              void* d_out, int out_size) {
    const float* in_feat = (const float*)d_in[0];
    const int*   ei      = (const int*)d_in[1];
    const float* W0      = (const float*)d_in[2];
    const float* b0      = (const float*)d_in[3];
    const float* W1      = (const float*)d_in[4];
    const float* b1      = (const float*)d_in[5];
    const float* lw0     = (const float*)d_in[6];
    const float* lb0     = (const float*)d_in[7];
    const float* lw2     = (const float*)d_in[8];
    const float* lb2     = (const float*)d_in[9];
    const float* lw3     = (const float*)d_in[10];
    const float* lb3     = (const float*)d_in[11];
    float* out = (float*)d_out;

    k_build<<<(EE + 255) / 256, 256>>>(ei);
    k_prep<<<(NN + 7) / 8, 256>>>(in_feat, W0, b0, W1);
    k_conv0<<<(NN + 23) / 24, 256>>>(W0, b0, W1);
    k_conv1<<<(NN + 23) / 24, 256>>>(b1);
    k_gemm<<<NCH, 512>>>(lw0);
    k_head<<<BB, 512>>>(lb0, lw2, lb2, lw3, lb3, out);
}